// round 2
// baseline (speedup 1.0000x reference)
#include <cuda_runtime.h>

// ============================================================================
// QuantumNAT: 4-qubit circuit, B=524288.
// out_q(x) = sum_{t in {1,cos,sin}^4} D_q[t] * prod_i basis_i[t_i]
// D (4 x 81 real coefficients) precomputed from weights by prep_kernel.
// Main kernel: 2 samples per thread using packed f32x2 FMA.
// ============================================================================

// Coefficient table: 81 entries x [D0,D0,D1,D1,D2,D2,D3,D3] (pre-duplicated
// for f32x2 operand use). 162 float4 = 2592 bytes.
__device__ float4 g_coefPacked[162];

// ---------------- complex helpers (prep only) ----------------
__device__ __forceinline__ float2 cmul(float2 a, float2 b) {
    return make_float2(a.x * b.x - a.y * b.y, a.x * b.y + a.y * b.x);
}
__device__ __forceinline__ float2 cmulcj(float2 a, float2 b) {  // conj(a)*b
    return make_float2(a.x * b.x + a.y * b.y, a.x * b.y - a.y * b.x);
}
__device__ __forceinline__ float2 cadd(float2 a, float2 b) {
    return make_float2(a.x + b.x, a.y + b.y);
}
__device__ __forceinline__ float2 csub(float2 a, float2 b) {
    return make_float2(a.x - b.x, a.y - b.y);
}

// 2x2 contraction against basis matrices:
//  t=0 (const): 1/2 (x00 + x11)
//  t=1 (cos):   1/2 (x00 - x11)
//  t=2 (sin):   1/2 * i * (x10 - x01)
__device__ __forceinline__ float2 ctr(float2 x00, float2 x01, float2 x10, float2 x11, int tsel) {
    if (tsel == 0) return make_float2(0.5f * (x00.x + x11.x), 0.5f * (x00.y + x11.y));
    if (tsel == 1) return make_float2(0.5f * (x00.x - x11.x), 0.5f * (x00.y - x11.y));
    return make_float2(0.5f * (x01.y - x10.y), 0.5f * (x10.x - x01.x));
}

// ============================================================================
// Prep kernel: one block, 256 threads.
//   1. Build 12 fused gates U = RZ*RY*RX from weights[3][4][3].
//   2. Build W (16x16 unitary of the variational circuit) column-by-column
//      in registers (qubit q <-> bit (3-q) of the 4-bit index).
//   3. M_q = W^dag Z_q W  (4 Hermitian 16x16).
//   4. Staged contraction over qubits 3,2,1,0 against the basis matrices
//      -> D_q[t0,t1,t2,t3] real, written pre-duplicated to g_coefPacked.
// ============================================================================
__global__ void prep_kernel(const float* __restrict__ w)
{
    __shared__ float2 Ug[12][2][2];
    __shared__ float2 Wm[16][16];             // Wm[m][col]
    __shared__ float2 Mq[4][16][16];
    __shared__ float2 T3[4][3][8][8];
    __shared__ float2 T2s[4][3][3][4][4];
    __shared__ float2 T1s[4][3][3][3][2][2];

    const int t = threadIdx.x;

    // --- 1. fused gate matrices -------------------------------------------
    if (t < 12) {
        float ax = 0.5f * w[t * 3 + 0];
        float ay = 0.5f * w[t * 3 + 1];
        float az = 0.5f * w[t * 3 + 2];
        float sx = sinf(ax), cx = cosf(ax);
        float sy = sinf(ay), cy = cosf(ay);
        float sz = sinf(az), cz = cosf(az);
        // RY*RX
        float2 a00 = make_float2( cy * cx,  sy * sx);
        float2 a01 = make_float2(-sy * cx, -cy * sx);
        float2 a10 = make_float2( sy * cx, -cy * sx);
        float2 a11 = make_float2( cy * cx, -sy * sx);
        // RZ rows: row0 *= e^{-i az}, row1 *= e^{+i az}
        float2 e0 = make_float2(cz, -sz);
        float2 e1 = make_float2(cz,  sz);
        Ug[t][0][0] = cmul(e0, a00); Ug[t][0][1] = cmul(e0, a01);
        Ug[t][1][0] = cmul(e1, a10); Ug[t][1][1] = cmul(e1, a11);
    }
    __syncthreads();

    // --- 2. W columns in registers ----------------------------------------
    if (t < 16) {
        float2 col[16];
        #pragma unroll
        for (int m = 0; m < 16; m++) col[m] = make_float2((m == t) ? 1.0f : 0.0f, 0.0f);

        #pragma unroll
        for (int l = 0; l < 3; l++) {
            #pragma unroll
            for (int i = 0; i < 4; i++) {
                float2 u00 = Ug[l * 4 + i][0][0], u01 = Ug[l * 4 + i][0][1];
                float2 u10 = Ug[l * 4 + i][1][0], u11 = Ug[l * 4 + i][1][1];
                const int str = 1 << (3 - i);
                #pragma unroll
                for (int p = 0; p < 8; p++) {
                    const int low = p & (str - 1);
                    const int m0  = ((p - low) << 1) | low;
                    const int m1  = m0 | str;
                    float2 a = col[m0], b = col[m1];
                    col[m0] = cadd(cmul(u00, a), cmul(u01, b));
                    col[m1] = cadd(cmul(u10, a), cmul(u11, b));
                }
            }
            // CNOT chain: control i -> target i+1
            #pragma unroll
            for (int i = 0; i < 3; i++) {
                const int cmask = 1 << (3 - i);
                const int tmask = 1 << (2 - i);
                #pragma unroll
                for (int m = 0; m < 16; m++) {
                    if ((m & cmask) && !(m & tmask)) {
                        float2 tmp = col[m];
                        col[m] = col[m | tmask];
                        col[m | tmask] = tmp;
                    }
                }
            }
        }
        #pragma unroll
        for (int m = 0; m < 16; m++) Wm[m][t] = col[m];
    }
    __syncthreads();

    // --- 3. M_q = W^dag Z_q W ---------------------------------------------
    {
        const int j = t >> 4, k = t & 15;
        float2 a0 = make_float2(0.f, 0.f), a1 = a0, a2 = a0, a3 = a0;
        #pragma unroll
        for (int m = 0; m < 16; m++) {
            float2 p = cmulcj(Wm[m][j], Wm[m][k]);
            a0 = (m & 8) ? csub(a0, p) : cadd(a0, p);
            a1 = (m & 4) ? csub(a1, p) : cadd(a1, p);
            a2 = (m & 2) ? csub(a2, p) : cadd(a2, p);
            a3 = (m & 1) ? csub(a3, p) : cadd(a3, p);
        }
        Mq[0][j][k] = a0; Mq[1][j][k] = a1; Mq[2][j][k] = a2; Mq[3][j][k] = a3;
    }
    __syncthreads();

    // --- 4a. contract qubit 3 (LSB) ---------------------------------------
    for (int e = t; e < 768; e += 256) {
        const int q = e / 192, r = e % 192, t3 = r / 64, ab = r % 64;
        const int a = ab >> 3, b = ab & 7;
        T3[q][t3][a][b] = ctr(Mq[q][2 * a][2 * b],     Mq[q][2 * a][2 * b + 1],
                              Mq[q][2 * a + 1][2 * b], Mq[q][2 * a + 1][2 * b + 1], t3);
    }
    __syncthreads();

    // --- 4b. contract qubit 2 ---------------------------------------------
    for (int e = t; e < 576; e += 256) {
        const int q = e / 144, r = e % 144, t2 = r / 48, r2 = r % 48;
        const int t3 = r2 / 16, ab = r2 % 16, a = ab >> 2, b = ab & 3;
        T2s[q][t2][t3][a][b] = ctr(T3[q][t3][2 * a][2 * b],     T3[q][t3][2 * a][2 * b + 1],
                                   T3[q][t3][2 * a + 1][2 * b], T3[q][t3][2 * a + 1][2 * b + 1], t2);
    }
    __syncthreads();

    // --- 4c. contract qubit 1 ---------------------------------------------
    for (int e = t; e < 432; e += 256) {
        const int q = e / 108, r = e % 108, t1 = r / 36, r2 = r % 36;
        const int t2 = r2 / 12, r3 = r2 % 12, t3 = r3 / 4, ab = r3 & 3;
        const int a = ab >> 1, b = ab & 1;
        T1s[q][t1][t2][t3][a][b] = ctr(T2s[q][t2][t3][2 * a][2 * b],     T2s[q][t2][t3][2 * a][2 * b + 1],
                                       T2s[q][t2][t3][2 * a + 1][2 * b], T2s[q][t2][t3][2 * a + 1][2 * b + 1], t1);
    }
    __syncthreads();

    // --- 4d. contract qubit 0, keep real part, write duplicated -----------
    for (int e = t; e < 324; e += 256) {
        const int q = e / 81, tt = e % 81;
        const int t0 = tt / 27, r = tt % 27, t1 = r / 9, r2 = r % 9, t2 = r2 / 3, t3 = r2 % 3;
        float2 x00 = T1s[q][t1][t2][t3][0][0];
        float2 x01 = T1s[q][t1][t2][t3][0][1];
        float2 x10 = T1s[q][t1][t2][t3][1][0];
        float2 x11 = T1s[q][t1][t2][t3][1][1];
        float d;
        if (t0 == 0)      d = 0.5f * (x00.x + x11.x);
        else if (t0 == 1) d = 0.5f * (x00.x - x11.x);
        else              d = 0.5f * (x01.y - x10.y);
        float2* out2 = reinterpret_cast<float2*>(g_coefPacked);
        out2[tt * 4 + q] = make_float2(d, d);
    }
}

// ============================================================================
// Main kernel: 2 samples per thread, packed f32x2 arithmetic.
// ============================================================================
__device__ __forceinline__ unsigned long long pk(float a, float b) {
    unsigned long long r;
    asm("mov.b64 %0, {%1, %2};" : "=l"(r) : "f"(a), "f"(b));
    return r;
}
__device__ __forceinline__ void upk(float& a, float& b, unsigned long long v) {
    asm("mov.b64 {%0, %1}, %2;" : "=f"(a), "=f"(b) : "l"(v));
}
__device__ __forceinline__ unsigned long long m2(unsigned long long a, unsigned long long b) {
    unsigned long long r;
    asm("mul.rn.f32x2 %0, %1, %2;" : "=l"(r) : "l"(a), "l"(b));
    return r;
}
__device__ __forceinline__ unsigned long long f2(unsigned long long a, unsigned long long b,
                                                 unsigned long long c) {
    unsigned long long r;
    asm("fma.rn.f32x2 %0, %1, %2, %3;" : "=l"(r) : "l"(a), "l"(b), "l"(c));
    return r;
}

__global__ __launch_bounds__(256)
void qnat_main(const float4* __restrict__ x, float4* __restrict__ out, int nPairs)
{
    __shared__ float4 sc4[162];
    for (int i = threadIdx.x; i < 162; i += 256) sc4[i] = g_coefPacked[i];
    __syncthreads();
    const ulonglong2* sc = reinterpret_cast<const ulonglong2*>(sc4);

    const int gid = blockIdx.x * 256 + threadIdx.x;
    if (gid >= nPairs) return;

    const float4 xa = x[2 * gid];
    const float4 xb = x[2 * gid + 1];

    float sA0, cA0, sA1, cA1, sA2, cA2, sA3, cA3;
    float sB0, cB0, sB1, cB1, sB2, cB2, sB3, cB3;
    __sincosf(xa.x, &sA0, &cA0);  __sincosf(xb.x, &sB0, &cB0);
    __sincosf(xa.y, &sA1, &cA1);  __sincosf(xb.y, &sB1, &cB1);
    __sincosf(xa.z, &sA2, &cA2);  __sincosf(xb.z, &sB2, &cB2);
    __sincosf(xa.w, &sA3, &cA3);  __sincosf(xb.w, &sB3, &cB3);

    const unsigned long long c0 = pk(cA0, cB0), s0 = pk(sA0, sB0);
    const unsigned long long c1 = pk(cA1, cB1), s1 = pk(sA1, sB1);
    const unsigned long long c2 = pk(cA2, cB2), s2 = pk(sA2, sB2);
    const unsigned long long c3 = pk(cA3, cB3), s3 = pk(sA3, sB3);
    const unsigned long long ONE = pk(1.0f, 1.0f);

    unsigned long long b01[9], b23[9];
    b01[0] = ONE; b01[1] = c1;        b01[2] = s1;
    b01[3] = c0;  b01[4] = m2(c0, c1); b01[5] = m2(c0, s1);
    b01[6] = s0;  b01[7] = m2(s0, c1); b01[8] = m2(s0, s1);
    b23[0] = ONE; b23[1] = c3;        b23[2] = s3;
    b23[3] = c2;  b23[4] = m2(c2, c3); b23[5] = m2(c2, s3);
    b23[6] = s2;  b23[7] = m2(s2, c3); b23[8] = m2(s2, s3);

    const unsigned long long Z = pk(0.0f, 0.0f);
    unsigned long long a0 = Z, a1 = Z, a2 = Z, a3 = Z;

    #pragma unroll
    for (int j = 0; j < 9; j++) {
        unsigned long long i0 = Z, i1 = Z, i2 = Z, i3 = Z;
        #pragma unroll
        for (int k = 0; k < 9; k++) {
            const ulonglong2 cA = sc[(j * 9 + k) * 2 + 0];
            const ulonglong2 cB = sc[(j * 9 + k) * 2 + 1];
            i0 = f2(cA.x, b23[k], i0);
            i1 = f2(cA.y, b23[k], i1);
            i2 = f2(cB.x, b23[k], i2);
            i3 = f2(cB.y, b23[k], i3);
        }
        a0 = f2(b01[j], i0, a0);
        a1 = f2(b01[j], i1, a1);
        a2 = f2(b01[j], i2, a2);
        a3 = f2(b01[j], i3, a3);
    }

    float oA0, oB0, oA1, oB1, oA2, oB2, oA3, oB3;
    upk(oA0, oB0, a0); upk(oA1, oB1, a1); upk(oA2, oB2, a2); upk(oA3, oB3, a3);

    out[2 * gid]     = make_float4(oA0, oA1, oA2, oA3);
    out[2 * gid + 1] = make_float4(oB0, oB1, oB2, oB3);
}

// ============================================================================
extern "C" void kernel_launch(void* const* d_in, const int* in_sizes, int n_in,
                              void* d_out, int out_size)
{
    const float* x = (const float*)d_in[0];        // [B,4] float32
    const float* w = (const float*)d_in[1];        // [3,4,3] float32

    prep_kernel<<<1, 256>>>(w);

    const int B = in_sizes[0] / 4;                 // 524288
    const int nPairs = B / 2;                      // 262144 (B is even)
    const int grid = (nPairs + 255) / 256;         // 1024
    qnat_main<<<grid, 256>>>((const float4*)x, (float4*)d_out, nPairs);
}